// round 9
// baseline (speedup 1.0000x reference)
#include <cuda_runtime.h>
#include <cstdint>

// FP4RoundingPerturb — output layout (float32, flattened concat):
//   [0,      N)           y
//   [N,      2N)          codes (as float)
//   [2N,     2N+B)        scales (e8m0+127 as float), B=N/32
//   [2N+B,   2N+B+7)      shifted_bounds
//   [2N+B+7, 2N+B+7+8N)   weights   <-- base float offset ≡ 3 (mod 4)
//
// One warp: 128 consecutive elements, 4 steps of 32 (step = one amax block).
// Weights written output-major with TILE-WIDE slot numbering: the warp-tile's
// 1024 weight floats have an aligned-quad zone [1, 1021) = 255 quads; slot
// s = 32k+lane (k=0..7, slot 255 skipped). Slot s covers element m = s>>1:
//   even s: w1..w4 of m;  odd s: w5,w6,w7 of m + w0 of m+1.
// Step-seam quads (odd k, lane 31) pull next step's E via one extra shfl.
// Only the tile edges (first w0, last w5..w7) are scalar stores.

#define WARPS_PER_CTA 8
#define STEPS 4

__global__ void __launch_bounds__(32 * WARPS_PER_CTA, 7)
fp4_main(const float* __restrict__ x,
         const float* __restrict__ delta_raw,
         const float* __restrict__ bounds_base,
         const float* __restrict__ values_table,
         float* __restrict__ y,
         float* __restrict__ codes,
         float* __restrict__ scales,
         float* __restrict__ sb_out,
         float* __restrict__ weights,   // float offset ≡ 3 (mod 4)
         int n_elems) {
    const unsigned FULL = 0xffffffffu;
    int tid  = threadIdx.x;
    int warp = tid >> 5;
    int lane = tid & 31;
    int base = (blockIdx.x * WARPS_PER_CTA + warp) * (32 * STEPS);
    if (base >= n_elems) return;

    // ---- per-warp constants (prep fused): K_i = exp(sb_i/tau) ----
    int   li     = lane & 7;
    float shift  = 0.5f * tanhf(delta_raw[0]);
    float sb_own = bounds_base[(li < 7) ? li : 6] + shift;
    float K_own  = __expf(sb_own * 10.0f);

    if (blockIdx.x == 0 && tid < 7) sb_out[tid] = sb_own;

    float K0 = __shfl_sync(FULL, K_own, 0);
    float K1 = __shfl_sync(FULL, K_own, 1);
    float K2 = __shfl_sync(FULL, K_own, 2);
    float K3 = __shfl_sync(FULL, K_own, 3);
    float K4 = __shfl_sync(FULL, K_own, 4);
    float K5 = __shfl_sync(FULL, K_own, 5);
    float K6 = __shfl_sync(FULL, K_own, 6);

    // per-lane slot parity is fixed: hoist the K selection
    bool  odd = lane & 1;
    float KA0 = odd ? K4 : K0;
    float KA1 = odd ? K5 : K1;
    float KA2 = odd ? K6 : K2;
    float KA3 = odd ? K0 : K3;

    int srcA0 = lane >> 1;
    int src30 = (lane + 1) >> 1;   // E3 source: same elem (even) / next (odd)

    // prefetch the 4 coalesced step loads
    const float* xp = x + base + lane;
    float xr[STEPS];
    #pragma unroll
    for (int c = 0; c < STEPS; c++) xr[c] = xp[32 * c];

    float* Wg = weights + (size_t)base * 8;   // rel float 0 of this warp tile
    float  E[STEPS];
    float  sc[STEPS];

    // ========== Phase A: element-major (amax, scale, E, ord/v, y, codes) ======
    #pragma unroll
    for (int c = 0; c < STEPS; c++) {
        float xv = xr[c];
        float ax = fabsf(xv);
        float amax = __uint_as_float(
            __reduce_max_sync(FULL, __float_as_uint(ax)));

        // biased exponent be = e+127 = ceil(log2(amax/6)) + 127 via carry-add:
        // adding 0x7FFFFF carries into the exponent iff mantissa != 0 (exact ceil)
        int bits = __float_as_int(amax * (1.0f / 6.0f));
        int be = (bits + 0x007FFFFF) >> 23;
        be = max(be, 1);                             // floor at 2^-126
        float scale     = __int_as_float(be << 23);
        float inv_scale = __int_as_float((254 - be) << 23);
        sc[c] = (float)be;

        float xs = xv * inv_scale;                   // exact pow2 scaling
        float xa = fabsf(xs);
        E[c] = __expf(xa * -10.0f);                  // FMUL + MUFU.EX2

        // E2M1 quantize of t = xa - shift, round-half-DOWN (== strict >).
        // xa <= 6 always (scale >= amax/6); negative t falls through safely
        // under signed compares (hi false, g1/g2 false -> ord 0, v 0).
        float t  = xa - shift;
        int rb = (__float_as_int(t) + 0x001FFFFF) & 0xFFC00000;
        bool hi = rb >= 0x3F800000;                  // rounded value >= 1.0
        bool g1 = t > 0.25f;
        bool g2 = t > 0.75f;
        int  ord = hi ? ((rb >> 22) - 252) : ((int)g1 + (int)g2);
        float v  = hi ? __int_as_float(rb)
                      : (g2 ? 1.0f : (g1 ? 0.5f : 0.0f));

        __stcs(&y[base + 32 * c + lane], copysignf(v * scale, xs));
        __stcs(&codes[base + 32 * c + lane],
               (float)(((xs < 0.0f) ? 8 : 0) | ord));
    }

    // scales: 4 consecutive, 16B-aligned -> one STG.128 from lane 0
    if (lane == 0)
        __stcs((float4*)(scales + (base >> 5)),
               make_float4(sc[0], sc[1], sc[2], sc[3]));

    // tile leading scalar: w0 of element 0
    if (lane == 0) {
        float p0 = __fdividef(1.0f, fmaf(K0, E[0], 1.0f));
        __stcs(Wg, 1.0f - p0);
    }

    // ========== Phase B: tile-wide output-major weight slots ==========
    #pragma unroll
    for (int k = 0; k < 8; k++) {
        const int c = k >> 1;          // warp-uniform E register index
        const int j = k & 1;
        float Ec = E[c];
        float Ea = __shfl_sync(FULL, Ec, 16 * j + srcA0);
        float E3 = __shfl_sync(FULL, Ec, (16 * j + src30) & 31);
        if (j == 1 && k < 7) {         // step-seam: lane31 needs next step's E[.,0]
            float Es = __shfl_sync(FULL, E[c + 1], 0);
            if (lane == 31) E3 = Es;
        }

        float q0 = __fdividef(1.0f, fmaf(KA0, Ea, 1.0f));
        float q1 = __fdividef(1.0f, fmaf(KA1, Ea, 1.0f));
        float q2 = __fdividef(1.0f, fmaf(KA2, Ea, 1.0f));
        float q3 = __fdividef(1.0f, fmaf(KA3, E3, 1.0f));
        float q4 = __fdividef(1.0f, fmaf(K4,  Ea, 1.0f)); // even slots only

        float o0 = q0 - q1;
        float o1 = q1 - q2;
        float o2 = odd ? q2 : (q2 - q3);
        float o3 = odd ? (1.0f - q3) : (q3 - q4);

        if (k < 7 || lane < 31)        // slot 255 excluded (tile trailing)
            __stcs((float4*)(Wg + 4 * (32 * k + lane) + 1),
                   make_float4(o0, o1, o2, o3));
    }

    // tile trailing scalars: w5,w6,w7 of element 127
    if (lane == 31) {
        float Et = E[STEPS - 1];
        float p4 = __fdividef(1.0f, fmaf(K4, Et, 1.0f));
        float p5 = __fdividef(1.0f, fmaf(K5, Et, 1.0f));
        float p6 = __fdividef(1.0f, fmaf(K6, Et, 1.0f));
        __stcs(&Wg[1021], p4 - p5);
        __stcs(&Wg[1022], p5 - p6);
        __stcs(&Wg[1023], p6);
    }
}

extern "C" void kernel_launch(void* const* d_in, const int* in_sizes, int n_in,
                              void* d_out, int out_size) {
    const float* x      = (const float*)d_in[0];
    const float* delta  = (const float*)d_in[1];
    const float* bounds = (const float*)d_in[2];
    const float* vt     = (const float*)d_in[3];

    int N = in_sizes[0];
    int n_blocks = N / 32;

    float* out     = (float*)d_out;
    float* y       = out;
    float* codes   = out + (size_t)N;
    float* scales  = out + 2 * (size_t)N;
    float* sb_out  = scales + n_blocks;
    float* weights = sb_out + 7;

    int elems_per_cta = 32 * STEPS * WARPS_PER_CTA;
    int ctas = (N + elems_per_cta - 1) / elems_per_cta;
    fp4_main<<<ctas, 32 * WARPS_PER_CTA>>>(x, delta, bounds, vt,
                                           y, codes, scales, sb_out, weights, N);
}